// round 12
// baseline (speedup 1.0000x reference)
#include <cuda_runtime.h>
#include <cuda_fp16.h>
#include <math.h>
#include <stdint.h>

#define TOKENS 4096
#define DM     1024
#define DFF    4096
#define NE     8

// ---------------- static device scratch ----------------
static __device__ __half g_xh[(size_t)TOKENS * DM];            // 8 MB
static __device__ __half g_w1h[(size_t)NE * DM * DFF];         // 64 MB  [e][k][n]
static __device__ __half g_w2h[(size_t)NE * DFF * DM];         // 64 MB  [e][k][n]
static __device__ __half g_h[(size_t)NE * TOKENS * DFF];       // 256 MB
static __device__ float  g_y[(size_t)NE * TOKENS * DM];        // 128 MB
static __device__ int    g_tok[NE * TOKENS];
static __device__ float  g_gate[NE * TOKENS];
static __device__ int    g_pos[2 * TOKENS];
static __device__ int    g_cnt[NE];

// ---------------- PTX helpers (base sm_103 ISA only) ----------------
__device__ __forceinline__ uint32_t smem_to_u32(const void* p) {
    uint32_t a;
    asm("{ .reg .u64 t; cvta.to.shared.u64 t, %1; cvt.u32.u64 %0, t; }" : "=r"(a) : "l"(p));
    return a;
}
// .cg: bypass L1 allocation (stream-once data)
__device__ __forceinline__ void cp16(uint32_t dst, const void* src, uint32_t nbytes) {
    asm volatile("cp.async.cg.shared.global [%0], [%1], 16, %2;"
                 :: "r"(dst), "l"(src), "r"(nbytes) : "memory");
}
#define CP_COMMIT() asm volatile("cp.async.commit_group;" ::: "memory")

__device__ __forceinline__ void ldm_x4(uint32_t* r, uint32_t addr) {
    asm volatile("ldmatrix.sync.aligned.m8n8.x4.shared.b16 {%0,%1,%2,%3}, [%4];"
                 : "=r"(r[0]), "=r"(r[1]), "=r"(r[2]), "=r"(r[3]) : "r"(addr));
}
__device__ __forceinline__ void ldm_x4_t(uint32_t* r, uint32_t addr) {
    asm volatile("ldmatrix.sync.aligned.m8n8.x4.trans.shared.b16 {%0,%1,%2,%3}, [%4];"
                 : "=r"(r[0]), "=r"(r[1]), "=r"(r[2]), "=r"(r[3]) : "r"(addr));
}
__device__ __forceinline__ void mma16816(float* d, const uint32_t* a, uint32_t b0, uint32_t b1) {
    asm volatile(
        "mma.sync.aligned.m16n8k16.row.col.f32.f16.f16.f32 "
        "{%0,%1,%2,%3}, {%4,%5,%6,%7}, {%8,%9}, {%0,%1,%2,%3};"
        : "+f"(d[0]), "+f"(d[1]), "+f"(d[2]), "+f"(d[3])
        : "r"(a[0]), "r"(a[1]), "r"(a[2]), "r"(a[3]), "r"(b0), "r"(b1));
}

// gelu(v) = v * sigmoid(2z),  z = 0.79788456(v + 0.044715 v^3)
__device__ __forceinline__ float gelu_f(float v) {
    const float z2 = 1.5957691216057308f * (v + 0.044715f * v * v * v);
    return v / (1.f + __expf(-z2));
}

// ---------------- small kernels ----------------
__global__ void zero_cnt_kernel() { if (threadIdx.x < NE) g_cnt[threadIdx.x] = 0; }

__global__ void gate_kernel(const float* __restrict__ x,
                            const float* __restrict__ Wg,
                            const float* __restrict__ bg) {
    __shared__ float sWg[DM * NE];
    const int tid = threadIdx.x;
    for (int i = tid; i < DM * NE; i += 256) sWg[i] = Wg[i];
    __syncthreads();
    const int warp = tid >> 5, lane = tid & 31;
    const int t = blockIdx.x * 8 + warp;
    const float* xr = x + (size_t)t * DM;
    float acc[NE];
#pragma unroll
    for (int e = 0; e < NE; e++) acc[e] = 0.f;
    for (int i = 0; i < DM / 32; i++) {
        const int r = i * 32 + lane;
        const float xv = xr[r];
#pragma unroll
        for (int e = 0; e < NE; e++) acc[e] += xv * sWg[r * NE + e];
    }
#pragma unroll
    for (int e = 0; e < NE; e++)
#pragma unroll
        for (int off = 16; off > 0; off >>= 1)
            acc[e] += __shfl_xor_sync(0xFFFFFFFFu, acc[e], off);
    if (lane == 0) {
        float v[NE];
#pragma unroll
        for (int e = 0; e < NE; e++) v[e] = acc[e] + bg[e];
        int b0 = 0; float m0v = v[0];
#pragma unroll
        for (int e = 1; e < NE; e++) if (v[e] > m0v) { m0v = v[e]; b0 = e; }
        int b1i = (b0 == 0) ? 1 : 0; float m1v = v[(b0 == 0) ? 1 : 0];
#pragma unroll
        for (int e = 0; e < NE; e++)
            if (e != b0 && v[e] > m1v) { m1v = v[e]; b1i = e; }
        const float e1 = expf(m1v - m0v);
        const float s = 1.f + e1;
        int p = atomicAdd(&g_cnt[b0], 1);
        g_tok[b0 * TOKENS + p] = t; g_gate[b0 * TOKENS + p] = 1.f / s;
        g_pos[2 * t] = b0 * TOKENS + p;
        p = atomicAdd(&g_cnt[b1i], 1);
        g_tok[b1i * TOKENS + p] = t; g_gate[b1i * TOKENS + p] = e1 / s;
        g_pos[2 * t + 1] = b1i * TOKENS + p;
    }
}

// One kernel converts x, W1, W2 to fp16 (8 floats per thread).
#define XBLK  ((TOKENS * DM / 8) / 256)                       // 2048
#define WBLK  ((int)((NE * (size_t)DM * DFF / 8) / 256))      // 16384
__global__ void convert_all_kernel(const float* __restrict__ x,
                                   const float* __restrict__ W1,
                                   const float* __restrict__ W2) {
    const int b = blockIdx.x;
    const float* src;
    __half* dst;
    size_t i;
    if (b < XBLK) {
        src = x;   dst = g_xh;  i = (size_t)b * 256 + threadIdx.x;
    } else if (b < XBLK + WBLK) {
        src = W1;  dst = g_w1h; i = (size_t)(b - XBLK) * 256 + threadIdx.x;
    } else {
        src = W2;  dst = g_w2h; i = (size_t)(b - XBLK - WBLK) * 256 + threadIdx.x;
    }
    float4 a = ((const float4*)src)[2 * i];
    float4 c = ((const float4*)src)[2 * i + 1];
    __half h[8] = { __float2half_rn(a.x), __float2half_rn(a.y),
                    __float2half_rn(a.z), __float2half_rn(a.w),
                    __float2half_rn(c.x), __float2half_rn(c.y),
                    __float2half_rn(c.z), __float2half_rn(c.w) };
    ((uint4*)dst)[i] = *(uint4*)h;
}

__global__ void combine_kernel(float* __restrict__ out) {
    const int t = blockIdx.x;
    const int p0 = g_pos[2 * t], p1 = g_pos[2 * t + 1];
    const float ga = g_gate[p0], gb = g_gate[p1];
    const float4* y0 = (const float4*)(g_y + (size_t)p0 * DM);
    const float4* y1 = (const float4*)(g_y + (size_t)p1 * DM);
    float4* o = (float4*)(out + (size_t)t * DM);
    const int i = threadIdx.x;
    float4 a = y0[i], b = y1[i];
    o[i] = make_float4(ga * a.x + gb * b.x, ga * a.y + gb * b.y,
                       ga * a.z + gb * b.z, ga * a.w + gb * b.w);
}

// ---------------- grouped GEMMs: 128x128 tile, K-chunk 64, 3-stage cp.async ----
// 8 warps 2x4, warp tile 64x32. ONE __syncthreads per 64-K chunk (half the barriers
// of the 32-K pipeline); 4 ks-steps of dependence-free MMA chains per barrier.
#define ASTRIDE 72
#define BSTRIDE 136
#define ASTAGE  (128 * ASTRIDE * 2)
#define BSTAGE  (64 * BSTRIDE * 2)
#define STAGES  3
#define SMEM_GEMM (STAGES * (ASTAGE + BSTAGE))

template<int PHASE>
__global__ void __launch_bounds__(256, 2)
moe_gemm_kernel(const float* __restrict__ bias_g) {
    constexpr int KDIM = (PHASE == 1) ? DM : DFF;
    constexpr int NDIM = (PHASE == 1) ? DFF : DM;
    constexpr int NK = KDIM / 64;

    const __half* __restrict__ Wh = (PHASE == 1) ? g_w1h : g_w2h;  // device-side resolve

    const int e  = blockIdx.y;
    const int c  = g_cnt[e];
    const int m0 = blockIdx.x * 128;          // m innermost
    if (m0 >= c) return;
    const int n0 = blockIdx.z * 128;          // n outermost

    extern __shared__ __align__(1024) char smem[];
    const uint32_t su = smem_to_u32(smem);
    const uint32_t sA = su, sB = su + STAGES * ASTAGE;

    const int tid = threadIdx.x;
    const int wid = tid >> 5, lane = tid & 31;
    const int warp_m = wid >> 2, warp_n = wid & 3;   // 2 x 4, warp tile 64x32

    // ---- A source (fp16): row = tid>>1, 32 halves (4 x 16B) per thread ----
    const int arow = tid >> 1, acol = (tid & 1) * 32;
    const int slotA = m0 + arow;
    const bool avalid = slotA < c;
    const __half* aptr;
    if (PHASE == 1) {
        const int tok = avalid ? g_tok[e * TOKENS + slotA] : 0;
        aptr = g_xh + (size_t)tok * DM;
    } else {
        aptr = g_h + ((size_t)e * TOKENS + (avalid ? slotA : 0)) * DFF;
    }
    const uint32_t abytes = (PHASE == 2 || avalid) ? 16u : 0u;

    // ---- B source (fp16): row = tid>>2 (64 rows), 32 halves per thread ----
    const int brow = tid >> 2, bcol = (tid & 3) * 32;
    const __half* bbase = Wh + (size_t)e * KDIM * NDIM + n0 + bcol;

    auto loadAB = [&](int kt, int s) {
        const uint32_t ad = sA + s * ASTAGE + (arow * ASTRIDE + acol) * 2;
        const __half* as = aptr + kt * 64 + acol;
#pragma unroll
        for (int i = 0; i < 4; i++) cp16(ad + i * 16, as + i * 8, abytes);
        const uint32_t bd = sB + s * BSTAGE + (brow * BSTRIDE + bcol) * 2;
        const __half* bs = bbase + (size_t)(kt * 64 + brow) * NDIM;
#pragma unroll
        for (int i = 0; i < 4; i++) cp16(bd + i * 16, bs + i * 8, 16);
    };

    float acc[4][4][4];
#pragma unroll
    for (int i = 0; i < 4; i++)
#pragma unroll
        for (int j = 0; j < 4; j++)
#pragma unroll
            for (int q = 0; q < 4; q++) acc[i][j][q] = 0.f;

    auto compute_stage = [&](int s) {
        const uint32_t ab = sA + s * ASTAGE;
        const uint32_t bb = sB + s * BSTAGE;
#pragma unroll
        for (int ks = 0; ks < 4; ks++) {
            uint32_t af[4][4];
#pragma unroll
            for (int mt = 0; mt < 4; mt++) {
                const uint32_t addr = ab +
                    ((warp_m * 64 + mt * 16 + (lane & 15)) * ASTRIDE +
                     ks * 16 + (lane >> 4) * 8) * 2;
                ldm_x4(af[mt], addr);
            }
            uint32_t bf[2][4];
#pragma unroll
            for (int np = 0; np < 2; np++) {
                const uint32_t k = ks * 16 + (lane & 7) + ((lane >> 3) & 1) * 8;
                const uint32_t col = warp_n * 32 + np * 16 + (lane >> 4) * 8;
                ldm_x4_t(bf[np], bb + (k * BSTRIDE + col) * 2);
            }
#pragma unroll
            for (int mt = 0; mt < 4; mt++)
#pragma unroll
                for (int nt = 0; nt < 4; nt++)
                    mma16816(acc[mt][nt], af[mt],
                             bf[nt >> 1][(nt & 1) * 2], bf[nt >> 1][(nt & 1) * 2 + 1]);
        }
    };

    // ---- prologue: fill stages 0..1 (2 commit groups) ----
#pragma unroll
    for (int p = 0; p < 2; p++) {
        if (p < NK) loadAB(p, p);
        CP_COMMIT();
    }

    // ---- mainloop: one sync per 64-K chunk; always commit so wait(1) <=> kt done ----
    for (int kt = 0; kt < NK; kt++) {
        asm volatile("cp.async.wait_group 1;" ::: "memory");
        __syncthreads();                    // stage kt readable; stage (kt+2)%3 free
        if (kt + 2 < NK) loadAB(kt + 2, (kt + 2) % STAGES);
        CP_COMMIT();
        compute_stage(kt % STAGES);
    }

    // ---- epilogue ----
    const float* bias = bias_g + (size_t)e * NDIM;
#pragma unroll
    for (int mt = 0; mt < 4; mt++) {
#pragma unroll
        for (int rh = 0; rh < 2; rh++) {
            const int r = warp_m * 64 + mt * 16 + (lane >> 2) + rh * 8;
            const int slot = m0 + r;
            if (slot < c) {
#pragma unroll
                for (int nt = 0; nt < 4; nt++) {
                    const int col = n0 + warp_n * 32 + nt * 8 + (lane & 3) * 2;
                    const float v0 = acc[mt][nt][rh * 2 + 0] + __ldg(&bias[col]);
                    const float v1 = acc[mt][nt][rh * 2 + 1] + __ldg(&bias[col + 1]);
                    if (PHASE == 1) {
                        __half2 hv = __floats2half2_rn(gelu_f(v0), gelu_f(v1));
                        *(__half2*)(g_h + ((size_t)e * TOKENS + slot) * DFF + col) = hv;
                    } else {
                        *(float2*)(g_y + ((size_t)e * TOKENS + slot) * DM + col) =
                            make_float2(v0, v1);
                    }
                }
            }
        }
    }
}

// ---------------- launch ----------------
extern "C" void kernel_launch(void* const* d_in, const int* in_sizes, int n_in,
                              void* d_out, int out_size) {
    const float* x  = (const float*)d_in[0];
    const float* Wg = (const float*)d_in[1];
    const float* bg = (const float*)d_in[2];
    const float* W1 = (const float*)d_in[3];
    const float* b1 = (const float*)d_in[4];
    const float* W2 = (const float*)d_in[5];
    const float* b2 = (const float*)d_in[6];
    float* out = (float*)d_out;

    cudaFuncSetAttribute(moe_gemm_kernel<1>,
                         cudaFuncAttributeMaxDynamicSharedMemorySize, SMEM_GEMM);
    cudaFuncSetAttribute(moe_gemm_kernel<2>,
                         cudaFuncAttributeMaxDynamicSharedMemorySize, SMEM_GEMM);

    // launch order keeps gemm1 at position 4 (= the launch ncu captures)
    zero_cnt_kernel<<<1, 32>>>();                                   // 1
    gate_kernel<<<TOKENS / 8, 256>>>(x, Wg, bg);                    // 2
    convert_all_kernel<<<XBLK + 2 * WBLK, 256>>>(x, W1, W2);        // 3

    dim3 g1(TOKENS / 128, NE, DFF / 128);   // m innermost, n outermost
    moe_gemm_kernel<1><<<g1, 256, SMEM_GEMM>>>(b1);                 // 4
    dim3 g2(TOKENS / 128, NE, DM / 128);
    moe_gemm_kernel<2><<<g2, 256, SMEM_GEMM>>>(b2);                 // 5

    combine_kernel<<<TOKENS, 256>>>(out);                           // 6
}

// round 13
// speedup vs baseline: 1.1542x; 1.1542x over previous
#include <cuda_runtime.h>
#include <cuda_fp16.h>
#include <math.h>
#include <stdint.h>

#define TOKENS 4096
#define DM     1024
#define DFF    4096
#define NE     8

// ---------------- static device scratch ----------------
static __device__ __half g_xh[(size_t)TOKENS * DM];            // 8 MB
static __device__ __half g_w1h[(size_t)NE * DM * DFF];         // 64 MB  [e][k][n]
static __device__ __half g_w2h[(size_t)NE * DFF * DM];         // 64 MB  [e][k][n]
static __device__ __half g_h[(size_t)NE * TOKENS * DFF];       // 256 MB
static __device__ float  g_y[(size_t)NE * TOKENS * DM];        // 128 MB
static __device__ int    g_tok[NE * TOKENS];
static __device__ float  g_gate[NE * TOKENS];
static __device__ int    g_pos[2 * TOKENS];
static __device__ int    g_cnt[NE];

// ---------------- PTX helpers (base sm_103 ISA only) ----------------
__device__ __forceinline__ uint32_t smem_to_u32(const void* p) {
    uint32_t a;
    asm("{ .reg .u64 t; cvta.to.shared.u64 t, %1; cvt.u32.u64 %0, t; }" : "=r"(a) : "l"(p));
    return a;
}
// .cg: bypass L1 allocation (stream-once data)
__device__ __forceinline__ void cp16(uint32_t dst, const void* src, uint32_t nbytes) {
    asm volatile("cp.async.cg.shared.global [%0], [%1], 16, %2;"
                 :: "r"(dst), "l"(src), "r"(nbytes) : "memory");
}
#define CP_COMMIT() asm volatile("cp.async.commit_group;" ::: "memory")

__device__ __forceinline__ void ldm_x4(uint32_t* r, uint32_t addr) {
    asm volatile("ldmatrix.sync.aligned.m8n8.x4.shared.b16 {%0,%1,%2,%3}, [%4];"
                 : "=r"(r[0]), "=r"(r[1]), "=r"(r[2]), "=r"(r[3]) : "r"(addr));
}
__device__ __forceinline__ void ldm_x4_t(uint32_t* r, uint32_t addr) {
    asm volatile("ldmatrix.sync.aligned.m8n8.x4.trans.shared.b16 {%0,%1,%2,%3}, [%4];"
                 : "=r"(r[0]), "=r"(r[1]), "=r"(r[2]), "=r"(r[3]) : "r"(addr));
}
__device__ __forceinline__ void mma16816(float* d, const uint32_t* a, uint32_t b0, uint32_t b1) {
    asm volatile(
        "mma.sync.aligned.m16n8k16.row.col.f32.f16.f16.f32 "
        "{%0,%1,%2,%3}, {%4,%5,%6,%7}, {%8,%9}, {%0,%1,%2,%3};"
        : "+f"(d[0]), "+f"(d[1]), "+f"(d[2]), "+f"(d[3])
        : "r"(a[0]), "r"(a[1]), "r"(a[2]), "r"(a[3]), "r"(b0), "r"(b1));
}

// gelu(v) = v * sigmoid(2z),  z = 0.79788456(v + 0.044715 v^3)
__device__ __forceinline__ float gelu_f(float v) {
    const float z2 = 1.5957691216057308f * (v + 0.044715f * v * v * v);
    return v / (1.f + __expf(-z2));
}

// ---------------- small kernels ----------------
__global__ void zero_cnt_kernel() { if (threadIdx.x < NE) g_cnt[threadIdx.x] = 0; }

__global__ void gate_kernel(const float* __restrict__ x,
                            const float* __restrict__ Wg,
                            const float* __restrict__ bg) {
    __shared__ float sWg[DM * NE];
    const int tid = threadIdx.x;
    for (int i = tid; i < DM * NE; i += 256) sWg[i] = Wg[i];
    __syncthreads();
    const int warp = tid >> 5, lane = tid & 31;
    const int t = blockIdx.x * 8 + warp;
    const float* xr = x + (size_t)t * DM;
    float acc[NE];
#pragma unroll
    for (int e = 0; e < NE; e++) acc[e] = 0.f;
    for (int i = 0; i < DM / 32; i++) {
        const int r = i * 32 + lane;
        const float xv = xr[r];
#pragma unroll
        for (int e = 0; e < NE; e++) acc[e] += xv * sWg[r * NE + e];
    }
#pragma unroll
    for (int e = 0; e < NE; e++)
#pragma unroll
        for (int off = 16; off > 0; off >>= 1)
            acc[e] += __shfl_xor_sync(0xFFFFFFFFu, acc[e], off);
    if (lane == 0) {
        float v[NE];
#pragma unroll
        for (int e = 0; e < NE; e++) v[e] = acc[e] + bg[e];
        int b0 = 0; float m0v = v[0];
#pragma unroll
        for (int e = 1; e < NE; e++) if (v[e] > m0v) { m0v = v[e]; b0 = e; }
        int b1i = (b0 == 0) ? 1 : 0; float m1v = v[(b0 == 0) ? 1 : 0];
#pragma unroll
        for (int e = 0; e < NE; e++)
            if (e != b0 && v[e] > m1v) { m1v = v[e]; b1i = e; }
        const float e1 = expf(m1v - m0v);
        const float s = 1.f + e1;
        int p = atomicAdd(&g_cnt[b0], 1);
        g_tok[b0 * TOKENS + p] = t; g_gate[b0 * TOKENS + p] = 1.f / s;
        g_pos[2 * t] = b0 * TOKENS + p;
        p = atomicAdd(&g_cnt[b1i], 1);
        g_tok[b1i * TOKENS + p] = t; g_gate[b1i * TOKENS + p] = e1 / s;
        g_pos[2 * t + 1] = b1i * TOKENS + p;
    }
}

// One kernel converts x, W1, W2 to fp16 (8 floats per thread).
#define XBLK  ((TOKENS * DM / 8) / 256)                       // 2048
#define WBLK  ((int)((NE * (size_t)DM * DFF / 8) / 256))      // 16384
__global__ void convert_all_kernel(const float* __restrict__ x,
                                   const float* __restrict__ W1,
                                   const float* __restrict__ W2) {
    const int b = blockIdx.x;
    const float* src;
    __half* dst;
    size_t i;
    if (b < XBLK) {
        src = x;   dst = g_xh;  i = (size_t)b * 256 + threadIdx.x;
    } else if (b < XBLK + WBLK) {
        src = W1;  dst = g_w1h; i = (size_t)(b - XBLK) * 256 + threadIdx.x;
    } else {
        src = W2;  dst = g_w2h; i = (size_t)(b - XBLK - WBLK) * 256 + threadIdx.x;
    }
    float4 a = ((const float4*)src)[2 * i];
    float4 c = ((const float4*)src)[2 * i + 1];
    __half h[8] = { __float2half_rn(a.x), __float2half_rn(a.y),
                    __float2half_rn(a.z), __float2half_rn(a.w),
                    __float2half_rn(c.x), __float2half_rn(c.y),
                    __float2half_rn(c.z), __float2half_rn(c.w) };
    ((uint4*)dst)[i] = *(uint4*)h;
}

__global__ void combine_kernel(float* __restrict__ out) {
    const int t = blockIdx.x;
    const int p0 = g_pos[2 * t], p1 = g_pos[2 * t + 1];
    const float ga = g_gate[p0], gb = g_gate[p1];
    const float4* y0 = (const float4*)(g_y + (size_t)p0 * DM);
    const float4* y1 = (const float4*)(g_y + (size_t)p1 * DM);
    float4* o = (float4*)(out + (size_t)t * DM);
    const int i = threadIdx.x;
    float4 a = y0[i], b = y1[i];
    o[i] = make_float4(ga * a.x + gb * b.x, ga * a.y + gb * b.y,
                       ga * a.z + gb * b.z, ga * a.w + gb * b.w);
}

// ---------------- grouped GEMMs: 128x128 tile, K-chunk 32, 6 stages ----
// 8 warps 2x4, warp tile 64x32. R10 smem geometry (ASTRIDE 40 / BSTRIDE 136).
// TWO chunks per barrier: one wait_group+__syncthreads per 64 K, 64 MMAs/warp
// between barriers; cp.async groups are chunk PAIRS (2 pairs in flight).
#define ASTRIDE 40
#define BSTRIDE 136
#define ASTAGE  (128 * ASTRIDE * 2)
#define BSTAGE  (32 * BSTRIDE * 2)
#define STAGES  6
#define SMEM_GEMM (STAGES * (ASTAGE + BSTAGE))

template<int PHASE>
__global__ void __launch_bounds__(256, 2)
moe_gemm_kernel(const float* __restrict__ bias_g) {
    constexpr int KDIM = (PHASE == 1) ? DM : DFF;
    constexpr int NDIM = (PHASE == 1) ? DFF : DM;
    constexpr int NK = KDIM / 32;               // 32 or 128 (even)

    const __half* __restrict__ Wh = (PHASE == 1) ? g_w1h : g_w2h;  // device-side resolve

    const int e  = blockIdx.y;
    const int c  = g_cnt[e];
    const int m0 = blockIdx.x * 128;          // m innermost
    if (m0 >= c) return;
    const int n0 = blockIdx.z * 128;          // n outermost

    extern __shared__ __align__(1024) char smem[];
    const uint32_t su = smem_to_u32(smem);
    const uint32_t sA = su, sB = su + STAGES * ASTAGE;

    const int tid = threadIdx.x;
    const int wid = tid >> 5, lane = tid & 31;
    const int warp_m = wid >> 2, warp_n = wid & 3;   // 2 x 4, warp tile 64x32

    // ---- A source (fp16): row = tid>>1, 2 x 16B per thread ----
    const int arow = tid >> 1, ac0 = (tid & 1) * 2;
    const int slotA = m0 + arow;
    const bool avalid = slotA < c;
    const __half* aptr;
    if (PHASE == 1) {
        const int tok = avalid ? g_tok[e * TOKENS + slotA] : 0;
        aptr = g_xh + (size_t)tok * DM;
    } else {
        aptr = g_h + ((size_t)e * TOKENS + (avalid ? slotA : 0)) * DFF;
    }
    const uint32_t abytes = (PHASE == 2 || avalid) ? 16u : 0u;

    // ---- B source (fp16): row = tid>>3 (32 rows), 16 halves per thread ----
    const int brow = tid >> 3, bcol = (tid & 7) * 16;
    const __half* bbase = Wh + (size_t)e * KDIM * NDIM + n0 + bcol;

    auto loadAB = [&](int kt, int s) {
        const uint32_t ad = sA + s * ASTAGE + (arow * ASTRIDE + ac0 * 8) * 2;
        const __half* as = aptr + kt * 32 + ac0 * 8;
        cp16(ad, as, abytes);
        cp16(ad + 16, as + 8, abytes);
        const uint32_t bd = sB + s * BSTAGE + (brow * BSTRIDE + bcol) * 2;
        const __half* bs = bbase + (size_t)(kt * 32 + brow) * NDIM;
        cp16(bd, bs, 16);
        cp16(bd + 16, bs + 8, 16);
    };

    float acc[4][4][4];
#pragma unroll
    for (int i = 0; i < 4; i++)
#pragma unroll
        for (int j = 0; j < 4; j++)
#pragma unroll
            for (int q = 0; q < 4; q++) acc[i][j][q] = 0.f;

    auto compute_stage = [&](int s) {
        const uint32_t ab = sA + s * ASTAGE;
        const uint32_t bb = sB + s * BSTAGE;
#pragma unroll
        for (int ks = 0; ks < 2; ks++) {
            uint32_t af[4][4];
#pragma unroll
            for (int mt = 0; mt < 4; mt++) {
                const uint32_t addr = ab +
                    ((warp_m * 64 + mt * 16 + (lane & 15)) * ASTRIDE +
                     ks * 16 + (lane >> 4) * 8) * 2;
                ldm_x4(af[mt], addr);
            }
            uint32_t bf[2][4];
#pragma unroll
            for (int np = 0; np < 2; np++) {
                const uint32_t k = ks * 16 + (lane & 7) + ((lane >> 3) & 1) * 8;
                const uint32_t col = warp_n * 32 + np * 16 + (lane >> 4) * 8;
                ldm_x4_t(bf[np], bb + (k * BSTRIDE + col) * 2);
            }
#pragma unroll
            for (int mt = 0; mt < 4; mt++)
#pragma unroll
                for (int nt = 0; nt < 4; nt++)
                    mma16816(acc[mt][nt], af[mt],
                             bf[nt >> 1][(nt & 1) * 2], bf[nt >> 1][(nt & 1) * 2 + 1]);
        }
    };

    // ---- prologue: chunks 0..3 as 2 pair-groups ----
    loadAB(0, 0); loadAB(1, 1); CP_COMMIT();
    loadAB(2, 2); loadAB(3, 3); CP_COMMIT();

    // ---- mainloop: one barrier per chunk PAIR ----
    for (int kt = 0; kt < NK; kt += 2) {
        asm volatile("cp.async.wait_group 1;" ::: "memory");   // pair kt resident
        __syncthreads();            // stages kt%6,(kt+1)%6 readable; (kt+4..5)%6 free
        if (kt + 4 < NK) { loadAB(kt + 4, (kt + 4) % STAGES);
                           loadAB(kt + 5, (kt + 5) % STAGES); }
        CP_COMMIT();
        compute_stage(kt % STAGES);
        compute_stage((kt + 1) % STAGES);
    }

    // ---- epilogue ----
    const float* bias = bias_g + (size_t)e * NDIM;
#pragma unroll
    for (int mt = 0; mt < 4; mt++) {
#pragma unroll
        for (int rh = 0; rh < 2; rh++) {
            const int r = warp_m * 64 + mt * 16 + (lane >> 2) + rh * 8;
            const int slot = m0 + r;
            if (slot < c) {
#pragma unroll
                for (int nt = 0; nt < 4; nt++) {
                    const int col = n0 + warp_n * 32 + nt * 8 + (lane & 3) * 2;
                    const float v0 = acc[mt][nt][rh * 2 + 0] + __ldg(&bias[col]);
                    const float v1 = acc[mt][nt][rh * 2 + 1] + __ldg(&bias[col + 1]);
                    if (PHASE == 1) {
                        __half2 hv = __floats2half2_rn(gelu_f(v0), gelu_f(v1));
                        *(__half2*)(g_h + ((size_t)e * TOKENS + slot) * DFF + col) = hv;
                    } else {
                        *(float2*)(g_y + ((size_t)e * TOKENS + slot) * DM + col) =
                            make_float2(v0, v1);
                    }
                }
            }
        }
    }
}

// ---------------- launch ----------------
extern "C" void kernel_launch(void* const* d_in, const int* in_sizes, int n_in,
                              void* d_out, int out_size) {
    const float* x  = (const float*)d_in[0];
    const float* Wg = (const float*)d_in[1];
    const float* bg = (const float*)d_in[2];
    const float* W1 = (const float*)d_in[3];
    const float* b1 = (const float*)d_in[4];
    const float* W2 = (const float*)d_in[5];
    const float* b2 = (const float*)d_in[6];
    float* out = (float*)d_out;

    cudaFuncSetAttribute(moe_gemm_kernel<1>,
                         cudaFuncAttributeMaxDynamicSharedMemorySize, SMEM_GEMM);
    cudaFuncSetAttribute(moe_gemm_kernel<2>,
                         cudaFuncAttributeMaxDynamicSharedMemorySize, SMEM_GEMM);

    // launch order keeps gemm1 at position 4 (= the launch ncu captures)
    zero_cnt_kernel<<<1, 32>>>();                                   // 1
    gate_kernel<<<TOKENS / 8, 256>>>(x, Wg, bg);                    // 2
    convert_all_kernel<<<XBLK + 2 * WBLK, 256>>>(x, W1, W2);        // 3

    dim3 g1(TOKENS / 128, NE, DFF / 128);   // m innermost, n outermost
    moe_gemm_kernel<1><<<g1, 256, SMEM_GEMM>>>(b1);                 // 4
    dim3 g2(TOKENS / 128, NE, DM / 128);
    moe_gemm_kernel<2><<<g2, 256, SMEM_GEMM>>>(b2);                 // 5

    combine_kernel<<<TOKENS, 256>>>(out);                           // 6
}

// round 14
// speedup vs baseline: 1.2267x; 1.0628x over previous
#include <cuda_runtime.h>
#include <cuda_fp16.h>
#include <math.h>
#include <stdint.h>

#define TOKENS 4096
#define DM     1024
#define DFF    4096
#define NE     8

// ---------------- static device scratch ----------------
static __device__ __half g_xh[(size_t)TOKENS * DM];            // 8 MB
static __device__ __half g_w1h[(size_t)NE * DM * DFF];         // 64 MB  [e][k][n]
static __device__ __half g_w2h[(size_t)NE * DFF * DM];         // 64 MB  [e][k][n]
static __device__ __half g_h[(size_t)NE * TOKENS * DFF];       // 256 MB
static __device__ float  g_y[(size_t)NE * TOKENS * DM];        // 128 MB
static __device__ int    g_tok[NE * TOKENS];
static __device__ float  g_gate[NE * TOKENS];
static __device__ int    g_pos[2 * TOKENS];
static __device__ int    g_cnt[NE];

// ---------------- PTX helpers (base sm_103 ISA only) ----------------
__device__ __forceinline__ uint32_t smem_to_u32(const void* p) {
    uint32_t a;
    asm("{ .reg .u64 t; cvta.to.shared.u64 t, %1; cvt.u32.u64 %0, t; }" : "=r"(a) : "l"(p));
    return a;
}
// .cg: bypass L1 allocation (stream-once data)
__device__ __forceinline__ void cp16(uint32_t dst, const void* src, uint32_t nbytes) {
    asm volatile("cp.async.cg.shared.global [%0], [%1], 16, %2;"
                 :: "r"(dst), "l"(src), "r"(nbytes) : "memory");
}
#define CP_COMMIT() asm volatile("cp.async.commit_group;" ::: "memory")

__device__ __forceinline__ void ldm_x4(uint32_t* r, uint32_t addr) {
    asm volatile("ldmatrix.sync.aligned.m8n8.x4.shared.b16 {%0,%1,%2,%3}, [%4];"
                 : "=r"(r[0]), "=r"(r[1]), "=r"(r[2]), "=r"(r[3]) : "r"(addr));
}
__device__ __forceinline__ void ldm_x4_t(uint32_t* r, uint32_t addr) {
    asm volatile("ldmatrix.sync.aligned.m8n8.x4.trans.shared.b16 {%0,%1,%2,%3}, [%4];"
                 : "=r"(r[0]), "=r"(r[1]), "=r"(r[2]), "=r"(r[3]) : "r"(addr));
}
__device__ __forceinline__ void mma16816(float* d, const uint32_t* a, uint32_t b0, uint32_t b1) {
    asm volatile(
        "mma.sync.aligned.m16n8k16.row.col.f32.f16.f16.f32 "
        "{%0,%1,%2,%3}, {%4,%5,%6,%7}, {%8,%9}, {%0,%1,%2,%3};"
        : "+f"(d[0]), "+f"(d[1]), "+f"(d[2]), "+f"(d[3])
        : "r"(a[0]), "r"(a[1]), "r"(a[2]), "r"(a[3]), "r"(b0), "r"(b1));
}

// gelu(v) = v * sigmoid(2z),  z = 0.79788456(v + 0.044715 v^3)
__device__ __forceinline__ float gelu_f(float v) {
    const float z2 = 1.5957691216057308f * (v + 0.044715f * v * v * v);
    return v / (1.f + __expf(-z2));
}

// ---------------- small kernels ----------------
__global__ void zero_cnt_kernel() { if (threadIdx.x < NE) g_cnt[threadIdx.x] = 0; }

__global__ void gate_kernel(const float* __restrict__ x,
                            const float* __restrict__ Wg,
                            const float* __restrict__ bg) {
    __shared__ float sWg[DM * NE];
    const int tid = threadIdx.x;
    for (int i = tid; i < DM * NE; i += 256) sWg[i] = Wg[i];
    __syncthreads();
    const int warp = tid >> 5, lane = tid & 31;
    const int t = blockIdx.x * 8 + warp;
    const float* xr = x + (size_t)t * DM;
    float acc[NE];
#pragma unroll
    for (int e = 0; e < NE; e++) acc[e] = 0.f;
    for (int i = 0; i < DM / 32; i++) {
        const int r = i * 32 + lane;
        const float xv = xr[r];
#pragma unroll
        for (int e = 0; e < NE; e++) acc[e] += xv * sWg[r * NE + e];
    }
#pragma unroll
    for (int e = 0; e < NE; e++)
#pragma unroll
        for (int off = 16; off > 0; off >>= 1)
            acc[e] += __shfl_xor_sync(0xFFFFFFFFu, acc[e], off);
    if (lane == 0) {
        float v[NE];
#pragma unroll
        for (int e = 0; e < NE; e++) v[e] = acc[e] + bg[e];
        int b0 = 0; float m0v = v[0];
#pragma unroll
        for (int e = 1; e < NE; e++) if (v[e] > m0v) { m0v = v[e]; b0 = e; }
        int b1i = (b0 == 0) ? 1 : 0; float m1v = v[(b0 == 0) ? 1 : 0];
#pragma unroll
        for (int e = 0; e < NE; e++)
            if (e != b0 && v[e] > m1v) { m1v = v[e]; b1i = e; }
        const float e1 = expf(m1v - m0v);
        const float s = 1.f + e1;
        int p = atomicAdd(&g_cnt[b0], 1);
        g_tok[b0 * TOKENS + p] = t; g_gate[b0 * TOKENS + p] = 1.f / s;
        g_pos[2 * t] = b0 * TOKENS + p;
        p = atomicAdd(&g_cnt[b1i], 1);
        g_tok[b1i * TOKENS + p] = t; g_gate[b1i * TOKENS + p] = e1 / s;
        g_pos[2 * t + 1] = b1i * TOKENS + p;
    }
}

// converts x and W1 to fp16 (8 floats per thread)
#define XBLK  ((TOKENS * DM / 8) / 256)                       // 2048
#define WBLK  ((int)((NE * (size_t)DM * DFF / 8) / 256))      // 16384
__global__ void convert_xw1_kernel(const float* __restrict__ x,
                                   const float* __restrict__ W1) {
    const int b = blockIdx.x;
    const float* src;
    __half* dst;
    size_t i;
    if (b < XBLK) {
        src = x;   dst = g_xh;  i = (size_t)b * 256 + threadIdx.x;
    } else {
        src = W1;  dst = g_w1h; i = (size_t)(b - XBLK) * 256 + threadIdx.x;
    }
    float4 a = ((const float4*)src)[2 * i];
    float4 c = ((const float4*)src)[2 * i + 1];
    __half h[8] = { __float2half_rn(a.x), __float2half_rn(a.y),
                    __float2half_rn(a.z), __float2half_rn(a.w),
                    __float2half_rn(c.x), __float2half_rn(c.y),
                    __float2half_rn(c.z), __float2half_rn(c.w) };
    ((uint4*)dst)[i] = *(uint4*)h;
}

// converts W2 to fp16 (runs on side stream, overlapped with gemm1)
__global__ void convert_w2_kernel(const float* __restrict__ W2) {
    const size_t i = (size_t)blockIdx.x * 256 + threadIdx.x;
    float4 a = ((const float4*)W2)[2 * i];
    float4 c = ((const float4*)W2)[2 * i + 1];
    __half h[8] = { __float2half_rn(a.x), __float2half_rn(a.y),
                    __float2half_rn(a.z), __float2half_rn(a.w),
                    __float2half_rn(c.x), __float2half_rn(c.y),
                    __float2half_rn(c.z), __float2half_rn(c.w) };
    ((uint4*)g_w2h)[i] = *(uint4*)h;
}

__global__ void combine_kernel(float* __restrict__ out) {
    const int t = blockIdx.x;
    const int p0 = g_pos[2 * t], p1 = g_pos[2 * t + 1];
    const float ga = g_gate[p0], gb = g_gate[p1];
    const float4* y0 = (const float4*)(g_y + (size_t)p0 * DM);
    const float4* y1 = (const float4*)(g_y + (size_t)p1 * DM);
    float4* o = (float4*)(out + (size_t)t * DM);
    const int i = threadIdx.x;
    float4 a = y0[i], b = y1[i];
    o[i] = make_float4(ga * a.x + gb * b.x, ga * a.y + gb * b.y,
                       ga * a.z + gb * b.z, ga * a.w + gb * b.w);
}

// ---------------- grouped GEMMs: exact R10 config (best measured) ----------------
// 128x128 tile, K-chunk 32, 8 warps 2x4 (warp tile 64x32), 4-stage cp.async,
// wait_group(2) + one __syncthreads per chunk. ~HMMA roofline (983 MAC/cyc/SM).
#define ASTRIDE 40
#define BSTRIDE 136
#define ASTAGE  (128 * ASTRIDE * 2)
#define BSTAGE  (32 * BSTRIDE * 2)
#define STAGES  4
#define SMEM_GEMM (STAGES * (ASTAGE + BSTAGE))

template<int PHASE>
__global__ void __launch_bounds__(256, 2)
moe_gemm_kernel(const float* __restrict__ bias_g) {
    constexpr int KDIM = (PHASE == 1) ? DM : DFF;
    constexpr int NDIM = (PHASE == 1) ? DFF : DM;
    constexpr int NK = KDIM / 32;

    const __half* __restrict__ Wh = (PHASE == 1) ? g_w1h : g_w2h;  // device-side resolve

    const int e  = blockIdx.y;
    const int c  = g_cnt[e];
    const int m0 = blockIdx.x * 128;          // m innermost
    if (m0 >= c) return;
    const int n0 = blockIdx.z * 128;          // n outermost

    extern __shared__ __align__(1024) char smem[];
    const uint32_t su = smem_to_u32(smem);
    const uint32_t sA = su, sB = su + STAGES * ASTAGE;

    const int tid = threadIdx.x;
    const int wid = tid >> 5, lane = tid & 31;
    const int warp_m = wid >> 2, warp_n = wid & 3;   // 2 x 4, warp tile 64x32

    // ---- A source (fp16): row = tid>>1, 2 x 16B per thread ----
    const int arow = tid >> 1, ac0 = (tid & 1) * 2;
    const int slotA = m0 + arow;
    const bool avalid = slotA < c;
    const __half* aptr;
    if (PHASE == 1) {
        const int tok = avalid ? g_tok[e * TOKENS + slotA] : 0;
        aptr = g_xh + (size_t)tok * DM;
    } else {
        aptr = g_h + ((size_t)e * TOKENS + (avalid ? slotA : 0)) * DFF;
    }
    const uint32_t abytes = (PHASE == 2 || avalid) ? 16u : 0u;

    // ---- B source (fp16): row = tid>>3 (32 rows), 16 halves per thread ----
    const int brow = tid >> 3, bcol = (tid & 7) * 16;
    const __half* bbase = Wh + (size_t)e * KDIM * NDIM + n0 + bcol;

    auto loadAB = [&](int kt, int s) {
        const uint32_t ad = sA + s * ASTAGE + (arow * ASTRIDE + ac0 * 8) * 2;
        const __half* as = aptr + kt * 32 + ac0 * 8;
        cp16(ad, as, abytes);
        cp16(ad + 16, as + 8, abytes);
        const uint32_t bd = sB + s * BSTAGE + (brow * BSTRIDE + bcol) * 2;
        const __half* bs = bbase + (size_t)(kt * 32 + brow) * NDIM;
        cp16(bd, bs, 16);
        cp16(bd + 16, bs + 8, 16);
    };

    float acc[4][4][4];
#pragma unroll
    for (int i = 0; i < 4; i++)
#pragma unroll
        for (int j = 0; j < 4; j++)
#pragma unroll
            for (int q = 0; q < 4; q++) acc[i][j][q] = 0.f;

    auto compute_stage = [&](int s) {
        const uint32_t ab = sA + s * ASTAGE;
        const uint32_t bb = sB + s * BSTAGE;
#pragma unroll
        for (int ks = 0; ks < 2; ks++) {
            uint32_t af[4][4];
#pragma unroll
            for (int mt = 0; mt < 4; mt++) {
                const uint32_t addr = ab +
                    ((warp_m * 64 + mt * 16 + (lane & 15)) * ASTRIDE +
                     ks * 16 + (lane >> 4) * 8) * 2;
                ldm_x4(af[mt], addr);
            }
            uint32_t bf[2][4];
#pragma unroll
            for (int np = 0; np < 2; np++) {
                const uint32_t k = ks * 16 + (lane & 7) + ((lane >> 3) & 1) * 8;
                const uint32_t col = warp_n * 32 + np * 16 + (lane >> 4) * 8;
                ldm_x4_t(bf[np], bb + (k * BSTRIDE + col) * 2);
            }
#pragma unroll
            for (int mt = 0; mt < 4; mt++)
#pragma unroll
                for (int nt = 0; nt < 4; nt++)
                    mma16816(acc[mt][nt], af[mt],
                             bf[nt >> 1][(nt & 1) * 2], bf[nt >> 1][(nt & 1) * 2 + 1]);
        }
    };

    // ---- prologue: fill stages 0..2 (3 commit groups) ----
#pragma unroll
    for (int p = 0; p < 3; p++) {
        if (p < NK) loadAB(p, p);
        CP_COMMIT();
    }

    // ---- mainloop: one sync per chunk; always commit so wait(2) <=> kt done ----
    for (int kt = 0; kt < NK; kt++) {
        asm volatile("cp.async.wait_group 2;" ::: "memory");
        __syncthreads();                    // stage kt readable; stage (kt+3)%4 free
        if (kt + 3 < NK) loadAB(kt + 3, (kt + 3) % STAGES);
        CP_COMMIT();
        compute_stage(kt % STAGES);
    }

    // ---- epilogue ----
    const float* bias = bias_g + (size_t)e * NDIM;
#pragma unroll
    for (int mt = 0; mt < 4; mt++) {
#pragma unroll
        for (int rh = 0; rh < 2; rh++) {
            const int r = warp_m * 64 + mt * 16 + (lane >> 2) + rh * 8;
            const int slot = m0 + r;
            if (slot < c) {
#pragma unroll
                for (int nt = 0; nt < 4; nt++) {
                    const int col = n0 + warp_n * 32 + nt * 8 + (lane & 3) * 2;
                    const float v0 = acc[mt][nt][rh * 2 + 0] + __ldg(&bias[col]);
                    const float v1 = acc[mt][nt][rh * 2 + 1] + __ldg(&bias[col + 1]);
                    if (PHASE == 1) {
                        __half2 hv = __floats2half2_rn(gelu_f(v0), gelu_f(v1));
                        *(__half2*)(g_h + ((size_t)e * TOKENS + slot) * DFF + col) = hv;
                    } else {
                        *(float2*)(g_y + ((size_t)e * TOKENS + slot) * DM + col) =
                            make_float2(v0, v1);
                    }
                }
            }
        }
    }
}

// ---------------- lazily-created side stream + events (host-side only; created
// on the uncaptured correctness call, so nothing is created during capture) ----
static cudaStream_t side_stream() {
    static cudaStream_t s = nullptr;
    if (!s) cudaStreamCreateWithFlags(&s, cudaStreamNonBlocking);
    return s;
}
static cudaEvent_t side_event(int i) {
    static cudaEvent_t e[2] = {nullptr, nullptr};
    if (!e[i]) cudaEventCreateWithFlags(&e[i], cudaEventDisableTiming);
    return e[i];
}

// ---------------- launch ----------------
extern "C" void kernel_launch(void* const* d_in, const int* in_sizes, int n_in,
                              void* d_out, int out_size) {
    const float* x  = (const float*)d_in[0];
    const float* Wg = (const float*)d_in[1];
    const float* bg = (const float*)d_in[2];
    const float* W1 = (const float*)d_in[3];
    const float* b1 = (const float*)d_in[4];
    const float* W2 = (const float*)d_in[5];
    const float* b2 = (const float*)d_in[6];
    float* out = (float*)d_out;

    cudaFuncSetAttribute(moe_gemm_kernel<1>,
                         cudaFuncAttributeMaxDynamicSharedMemorySize, SMEM_GEMM);
    cudaFuncSetAttribute(moe_gemm_kernel<2>,
                         cudaFuncAttributeMaxDynamicSharedMemorySize, SMEM_GEMM);

    cudaStream_t s2 = side_stream();
    cudaEvent_t ev_fork = side_event(0), ev_w2 = side_event(1);

    // main stream
    zero_cnt_kernel<<<1, 32>>>();

    // fork: convert W2 on side stream, overlapping gate/convert_xw1/gemm1
    cudaEventRecord(ev_fork, 0);
    cudaStreamWaitEvent(s2, ev_fork, 0);
    convert_w2_kernel<<<WBLK, 256, 0, s2>>>(W2);
    cudaEventRecord(ev_w2, s2);

    gate_kernel<<<TOKENS / 8, 256>>>(x, Wg, bg);
    convert_xw1_kernel<<<XBLK + WBLK, 256>>>(x, W1);

    dim3 g1(TOKENS / 128, NE, DFF / 128);   // m innermost, n outermost
    moe_gemm_kernel<1><<<g1, 256, SMEM_GEMM>>>(b1);

    // join: gemm2 needs g_w2h
    cudaStreamWaitEvent(0, ev_w2, 0);
    dim3 g2(TOKENS / 128, NE, DM / 128);
    moe_gemm_kernel<2><<<g2, 256, SMEM_GEMM>>>(b2);

    combine_kernel<<<TOKENS, 256>>>(out);
}

// round 15
// speedup vs baseline: 1.2352x; 1.0069x over previous
#include <cuda_runtime.h>
#include <cuda_fp16.h>
#include <math.h>
#include <stdint.h>

#define TOKENS 4096
#define DM     1024
#define DFF    4096
#define NE     8

// ---------------- static device scratch ----------------
static __device__ __half g_xh[(size_t)TOKENS * DM];            // 8 MB
static __device__ __half g_w1h[(size_t)NE * DM * DFF];         // 64 MB  [e][k][n]
static __device__ __half g_w2h[(size_t)NE * DFF * DM];         // 64 MB  [e][k][n]
static __device__ __half g_h[(size_t)NE * TOKENS * DFF];       // 256 MB
static __device__ float  g_y[(size_t)NE * TOKENS * DM];        // 128 MB
static __device__ int    g_tok[NE * TOKENS];
static __device__ float  g_gate[NE * TOKENS];
static __device__ int    g_pos[2 * TOKENS];
static __device__ int    g_cnt[NE];

// ---------------- PTX helpers (base sm_103 ISA only) ----------------
__device__ __forceinline__ uint32_t smem_to_u32(const void* p) {
    uint32_t a;
    asm("{ .reg .u64 t; cvta.to.shared.u64 t, %1; cvt.u32.u64 %0, t; }" : "=r"(a) : "l"(p));
    return a;
}
// .cg: bypass L1 allocation (stream-once data)
__device__ __forceinline__ void cp16(uint32_t dst, const void* src, uint32_t nbytes) {
    asm volatile("cp.async.cg.shared.global [%0], [%1], 16, %2;"
                 :: "r"(dst), "l"(src), "r"(nbytes) : "memory");
}
#define CP_COMMIT() asm volatile("cp.async.commit_group;" ::: "memory")

__device__ __forceinline__ void ldm_x4(uint32_t* r, uint32_t addr) {
    asm volatile("ldmatrix.sync.aligned.m8n8.x4.shared.b16 {%0,%1,%2,%3}, [%4];"
                 : "=r"(r[0]), "=r"(r[1]), "=r"(r[2]), "=r"(r[3]) : "r"(addr));
}
__device__ __forceinline__ void ldm_x4_t(uint32_t* r, uint32_t addr) {
    asm volatile("ldmatrix.sync.aligned.m8n8.x4.trans.shared.b16 {%0,%1,%2,%3}, [%4];"
                 : "=r"(r[0]), "=r"(r[1]), "=r"(r[2]), "=r"(r[3]) : "r"(addr));
}
__device__ __forceinline__ void mma16816(float* d, const uint32_t* a, uint32_t b0, uint32_t b1) {
    asm volatile(
        "mma.sync.aligned.m16n8k16.row.col.f32.f16.f16.f32 "
        "{%0,%1,%2,%3}, {%4,%5,%6,%7}, {%8,%9}, {%0,%1,%2,%3};"
        : "+f"(d[0]), "+f"(d[1]), "+f"(d[2]), "+f"(d[3])
        : "r"(a[0]), "r"(a[1]), "r"(a[2]), "r"(a[3]), "r"(b0), "r"(b1));
}

// gelu(v) = v * sigmoid(2z),  z = 0.79788456(v + 0.044715 v^3)
__device__ __forceinline__ float gelu_f(float v) {
    const float z2 = 1.5957691216057308f * (v + 0.044715f * v * v * v);
    return v / (1.f + __expf(-z2));
}

// ---------------- small kernels ----------------
__global__ void zero_cnt_kernel() { if (threadIdx.x < NE) g_cnt[threadIdx.x] = 0; }

__global__ void gate_kernel(const float* __restrict__ x,
                            const float* __restrict__ Wg,
                            const float* __restrict__ bg) {
    __shared__ float sWg[DM * NE];
    const int tid = threadIdx.x;
    for (int i = tid; i < DM * NE; i += 256) sWg[i] = Wg[i];
    __syncthreads();
    const int warp = tid >> 5, lane = tid & 31;
    const int t = blockIdx.x * 8 + warp;
    const float* xr = x + (size_t)t * DM;
    float acc[NE];
#pragma unroll
    for (int e = 0; e < NE; e++) acc[e] = 0.f;
    for (int i = 0; i < DM / 32; i++) {
        const int r = i * 32 + lane;
        const float xv = xr[r];
#pragma unroll
        for (int e = 0; e < NE; e++) acc[e] += xv * sWg[r * NE + e];
    }
#pragma unroll
    for (int e = 0; e < NE; e++)
#pragma unroll
        for (int off = 16; off > 0; off >>= 1)
            acc[e] += __shfl_xor_sync(0xFFFFFFFFu, acc[e], off);
    if (lane == 0) {
        float v[NE];
#pragma unroll
        for (int e = 0; e < NE; e++) v[e] = acc[e] + bg[e];
        int b0 = 0; float m0v = v[0];
#pragma unroll
        for (int e = 1; e < NE; e++) if (v[e] > m0v) { m0v = v[e]; b0 = e; }
        int b1i = (b0 == 0) ? 1 : 0; float m1v = v[(b0 == 0) ? 1 : 0];
#pragma unroll
        for (int e = 0; e < NE; e++)
            if (e != b0 && v[e] > m1v) { m1v = v[e]; b1i = e; }
        const float e1 = expf(m1v - m0v);
        const float s = 1.f + e1;
        int p = atomicAdd(&g_cnt[b0], 1);
        g_tok[b0 * TOKENS + p] = t; g_gate[b0 * TOKENS + p] = 1.f / s;
        g_pos[2 * t] = b0 * TOKENS + p;
        p = atomicAdd(&g_cnt[b1i], 1);
        g_tok[b1i * TOKENS + p] = t; g_gate[b1i * TOKENS + p] = e1 / s;
        g_pos[2 * t + 1] = b1i * TOKENS + p;
    }
}

// converts x and W1 to fp16 (8 floats per thread)
#define XBLK  ((TOKENS * DM / 8) / 256)                       // 2048
#define WBLK  ((int)((NE * (size_t)DM * DFF / 8) / 256))      // 16384
__global__ void convert_xw1_kernel(const float* __restrict__ x,
                                   const float* __restrict__ W1) {
    const int b = blockIdx.x;
    const float* src;
    __half* dst;
    size_t i;
    if (b < XBLK) {
        src = x;   dst = g_xh;  i = (size_t)b * 256 + threadIdx.x;
    } else {
        src = W1;  dst = g_w1h; i = (size_t)(b - XBLK) * 256 + threadIdx.x;
    }
    float4 a = ((const float4*)src)[2 * i];
    float4 c = ((const float4*)src)[2 * i + 1];
    __half h[8] = { __float2half_rn(a.x), __float2half_rn(a.y),
                    __float2half_rn(a.z), __float2half_rn(a.w),
                    __float2half_rn(c.x), __float2half_rn(c.y),
                    __float2half_rn(c.z), __float2half_rn(c.w) };
    ((uint4*)dst)[i] = *(uint4*)h;
}

// converts W2 to fp16 (side stream, overlapped with gemm1's DRAM-idle window)
__global__ void convert_w2_kernel(const float* __restrict__ W2) {
    const size_t i = (size_t)blockIdx.x * 256 + threadIdx.x;
    float4 a = ((const float4*)W2)[2 * i];
    float4 c = ((const float4*)W2)[2 * i + 1];
    __half h[8] = { __float2half_rn(a.x), __float2half_rn(a.y),
                    __float2half_rn(a.z), __float2half_rn(a.w),
                    __float2half_rn(c.x), __float2half_rn(c.y),
                    __float2half_rn(c.z), __float2half_rn(c.w) };
    ((uint4*)g_w2h)[i] = *(uint4*)h;
}

__global__ void combine_kernel(float* __restrict__ out) {
    const int t = blockIdx.x;
    const int p0 = g_pos[2 * t], p1 = g_pos[2 * t + 1];
    const float ga = g_gate[p0], gb = g_gate[p1];
    const float4* y0 = (const float4*)(g_y + (size_t)p0 * DM);
    const float4* y1 = (const float4*)(g_y + (size_t)p1 * DM);
    float4* o = (float4*)(out + (size_t)t * DM);
    const int i = threadIdx.x;
    float4 a = y0[i], b = y1[i];
    o[i] = make_float4(ga * a.x + gb * b.x, ga * a.y + gb * b.y,
                       ga * a.z + gb * b.z, ga * a.w + gb * b.w);
}

// ---------------- grouped GEMMs: exact R10 config (best measured) ----------------
// 128x128 tile, K-chunk 32, 8 warps 2x4 (warp tile 64x32), 4-stage cp.async,
// wait_group(2) + one __syncthreads per chunk. ~95% of mma.sync MAC roofline.
#define ASTRIDE 40
#define BSTRIDE 136
#define ASTAGE  (128 * ASTRIDE * 2)
#define BSTAGE  (32 * BSTRIDE * 2)
#define STAGES  4
#define SMEM_GEMM (STAGES * (ASTAGE + BSTAGE))

template<int PHASE>
__global__ void __launch_bounds__(256, 2)
moe_gemm_kernel(const float* __restrict__ bias_g) {
    constexpr int KDIM = (PHASE == 1) ? DM : DFF;
    constexpr int NDIM = (PHASE == 1) ? DFF : DM;
    constexpr int NK = KDIM / 32;

    const __half* __restrict__ Wh = (PHASE == 1) ? g_w1h : g_w2h;  // device-side resolve

    const int e  = blockIdx.y;
    const int c  = g_cnt[e];
    const int m0 = blockIdx.x * 128;          // m innermost
    if (m0 >= c) return;
    const int n0 = blockIdx.z * 128;          // n outermost

    extern __shared__ __align__(1024) char smem[];
    const uint32_t su = smem_to_u32(smem);
    const uint32_t sA = su, sB = su + STAGES * ASTAGE;

    const int tid = threadIdx.x;
    const int wid = tid >> 5, lane = tid & 31;
    const int warp_m = wid >> 2, warp_n = wid & 3;   // 2 x 4, warp tile 64x32

    // ---- A source (fp16): row = tid>>1, 2 x 16B per thread ----
    const int arow = tid >> 1, ac0 = (tid & 1) * 2;
    const int slotA = m0 + arow;
    const bool avalid = slotA < c;
    const __half* aptr;
    if (PHASE == 1) {
        const int tok = avalid ? g_tok[e * TOKENS + slotA] : 0;
        aptr = g_xh + (size_t)tok * DM;
    } else {
        aptr = g_h + ((size_t)e * TOKENS + (avalid ? slotA : 0)) * DFF;
    }
    const uint32_t abytes = (PHASE == 2 || avalid) ? 16u : 0u;

    // ---- B source (fp16): row = tid>>3 (32 rows), 16 halves per thread ----
    const int brow = tid >> 3, bcol = (tid & 7) * 16;
    const __half* bbase = Wh + (size_t)e * KDIM * NDIM + n0 + bcol;

    auto loadAB = [&](int kt, int s) {
        const uint32_t ad = sA + s * ASTAGE + (arow * ASTRIDE + ac0 * 8) * 2;
        const __half* as = aptr + kt * 32 + ac0 * 8;
        cp16(ad, as, abytes);
        cp16(ad + 16, as + 8, abytes);
        const uint32_t bd = sB + s * BSTAGE + (brow * BSTRIDE + bcol) * 2;
        const __half* bs = bbase + (size_t)(kt * 32 + brow) * NDIM;
        cp16(bd, bs, 16);
        cp16(bd + 16, bs + 8, 16);
    };

    float acc[4][4][4];
#pragma unroll
    for (int i = 0; i < 4; i++)
#pragma unroll
        for (int j = 0; j < 4; j++)
#pragma unroll
            for (int q = 0; q < 4; q++) acc[i][j][q] = 0.f;

    auto compute_stage = [&](int s) {
        const uint32_t ab = sA + s * ASTAGE;
        const uint32_t bb = sB + s * BSTAGE;
#pragma unroll
        for (int ks = 0; ks < 2; ks++) {
            uint32_t af[4][4];
#pragma unroll
            for (int mt = 0; mt < 4; mt++) {
                const uint32_t addr = ab +
                    ((warp_m * 64 + mt * 16 + (lane & 15)) * ASTRIDE +
                     ks * 16 + (lane >> 4) * 8) * 2;
                ldm_x4(af[mt], addr);
            }
            uint32_t bf[2][4];
#pragma unroll
            for (int np = 0; np < 2; np++) {
                const uint32_t k = ks * 16 + (lane & 7) + ((lane >> 3) & 1) * 8;
                const uint32_t col = warp_n * 32 + np * 16 + (lane >> 4) * 8;
                ldm_x4_t(bf[np], bb + (k * BSTRIDE + col) * 2);
            }
#pragma unroll
            for (int mt = 0; mt < 4; mt++)
#pragma unroll
                for (int nt = 0; nt < 4; nt++)
                    mma16816(acc[mt][nt], af[mt],
                             bf[nt >> 1][(nt & 1) * 2], bf[nt >> 1][(nt & 1) * 2 + 1]);
        }
    };

    // ---- prologue: fill stages 0..2 (3 commit groups) ----
#pragma unroll
    for (int p = 0; p < 3; p++) {
        if (p < NK) loadAB(p, p);
        CP_COMMIT();
    }

    // ---- mainloop: one sync per chunk; always commit so wait(2) <=> kt done ----
    for (int kt = 0; kt < NK; kt++) {
        asm volatile("cp.async.wait_group 2;" ::: "memory");
        __syncthreads();                    // stage kt readable; stage (kt+3)%4 free
        if (kt + 3 < NK) loadAB(kt + 3, (kt + 3) % STAGES);
        CP_COMMIT();
        compute_stage(kt % STAGES);
    }

    // ---- epilogue ----
    const float* bias = bias_g + (size_t)e * NDIM;
#pragma unroll
    for (int mt = 0; mt < 4; mt++) {
#pragma unroll
        for (int rh = 0; rh < 2; rh++) {
            const int r = warp_m * 64 + mt * 16 + (lane >> 2) + rh * 8;
            const int slot = m0 + r;
            if (slot < c) {
#pragma unroll
                for (int nt = 0; nt < 4; nt++) {
                    const int col = n0 + warp_n * 32 + nt * 8 + (lane & 3) * 2;
                    const float v0 = acc[mt][nt][rh * 2 + 0] + __ldg(&bias[col]);
                    const float v1 = acc[mt][nt][rh * 2 + 1] + __ldg(&bias[col + 1]);
                    if (PHASE == 1) {
                        __half2 hv = __floats2half2_rn(gelu_f(v0), gelu_f(v1));
                        *(__half2*)(g_h + ((size_t)e * TOKENS + slot) * DFF + col) = hv;
                    } else {
                        *(float2*)(g_y + ((size_t)e * TOKENS + slot) * DM + col) =
                            make_float2(v0, v1);
                    }
                }
            }
        }
    }
}

// ---------------- lazily-created side stream + events (host-side only; created
// on the uncaptured correctness call, so nothing is created during capture) ----
static cudaStream_t side_stream() {
    static cudaStream_t s = nullptr;
    if (!s) cudaStreamCreateWithFlags(&s, cudaStreamNonBlocking);
    return s;
}
static cudaEvent_t side_event(int i) {
    static cudaEvent_t e[2] = {nullptr, nullptr};
    if (!e[i]) cudaEventCreateWithFlags(&e[i], cudaEventDisableTiming);
    return e[i];
}

// ---------------- launch ----------------
extern "C" void kernel_launch(void* const* d_in, const int* in_sizes, int n_in,
                              void* d_out, int out_size) {
    const float* x  = (const float*)d_in[0];
    const float* Wg = (const float*)d_in[1];
    const float* bg = (const float*)d_in[2];
    const float* W1 = (const float*)d_in[3];
    const float* b1 = (const float*)d_in[4];
    const float* W2 = (const float*)d_in[5];
    const float* b2 = (const float*)d_in[6];
    float* out = (float*)d_out;

    cudaFuncSetAttribute(moe_gemm_kernel<1>,
                         cudaFuncAttributeMaxDynamicSharedMemorySize, SMEM_GEMM);
    cudaFuncSetAttribute(moe_gemm_kernel<2>,
                         cudaFuncAttributeMaxDynamicSharedMemorySize, SMEM_GEMM);

    cudaStream_t s2 = side_stream();
    cudaEvent_t ev_fork = side_event(0), ev_w2 = side_event(1);

    // main stream: gating + fp16 conversion of x and W1 (DRAM-bound window)
    zero_cnt_kernel<<<1, 32>>>();
    gate_kernel<<<TOKENS / 8, 256>>>(x, Wg, bg);
    convert_xw1_kernel<<<XBLK + WBLK, 256>>>(x, W1);

    // fork AFTER the DRAM-bound converts: convert_w2 runs on the side stream
    // concurrently with gemm1 (DRAM=5% idle there), not with the converts.
    cudaEventRecord(ev_fork, 0);
    cudaStreamWaitEvent(s2, ev_fork, 0);
    convert_w2_kernel<<<WBLK, 256, 0, s2>>>(W2);
    cudaEventRecord(ev_w2, s2);

    dim3 g1(TOKENS / 128, NE, DFF / 128);   // m innermost, n outermost
    moe_gemm_kernel<1><<<g1, 256, SMEM_GEMM>>>(b1);

    // join: gemm2 needs g_w2h
    cudaStreamWaitEvent(0, ev_w2, 0);
    dim3 g2(TOKENS / 128, NE, DM / 128);
    moe_gemm_kernel<2><<<g2, 256, SMEM_GEMM>>>(b2);

    combine_kernel<<<TOKENS, 256>>>(out);
}

// round 16
// speedup vs baseline: 1.2586x; 1.0190x over previous
#include <cuda_runtime.h>
#include <cuda_fp16.h>
#include <math.h>
#include <stdint.h>

#define TOKENS 4096
#define DM     1024
#define DFF    4096
#define NE     8

// ---------------- static device scratch ----------------
static __device__ __half g_xh[(size_t)TOKENS * DM];            // 8 MB
static __device__ __half g_w1h[(size_t)NE * DM * DFF];         // 64 MB  [e][k][n]
static __device__ __half g_w2h[(size_t)NE * DFF * DM];         // 64 MB  [e][k][n]
static __device__ __half g_h[(size_t)NE * TOKENS * DFF];       // 256 MB
static __device__ int    g_tok[NE * TOKENS];
static __device__ float  g_gate[NE * TOKENS];
static __device__ int    g_cnt[NE];

// ---------------- PTX helpers (base sm_103 ISA only) ----------------
__device__ __forceinline__ uint32_t smem_to_u32(const void* p) {
    uint32_t a;
    asm("{ .reg .u64 t; cvta.to.shared.u64 t, %1; cvt.u32.u64 %0, t; }" : "=r"(a) : "l"(p));
    return a;
}
// .cg: bypass L1 allocation (stream-once data)
__device__ __forceinline__ void cp16(uint32_t dst, const void* src, uint32_t nbytes) {
    asm volatile("cp.async.cg.shared.global [%0], [%1], 16, %2;"
                 :: "r"(dst), "l"(src), "r"(nbytes) : "memory");
}
#define CP_COMMIT() asm volatile("cp.async.commit_group;" ::: "memory")

__device__ __forceinline__ void ldm_x4(uint32_t* r, uint32_t addr) {
    asm volatile("ldmatrix.sync.aligned.m8n8.x4.shared.b16 {%0,%1,%2,%3}, [%4];"
                 : "=r"(r[0]), "=r"(r[1]), "=r"(r[2]), "=r"(r[3]) : "r"(addr));
}
__device__ __forceinline__ void ldm_x4_t(uint32_t* r, uint32_t addr) {
    asm volatile("ldmatrix.sync.aligned.m8n8.x4.trans.shared.b16 {%0,%1,%2,%3}, [%4];"
                 : "=r"(r[0]), "=r"(r[1]), "=r"(r[2]), "=r"(r[3]) : "r"(addr));
}
__device__ __forceinline__ void mma16816(float* d, const uint32_t* a, uint32_t b0, uint32_t b1) {
    asm volatile(
        "mma.sync.aligned.m16n8k16.row.col.f32.f16.f16.f32 "
        "{%0,%1,%2,%3}, {%4,%5,%6,%7}, {%8,%9}, {%0,%1,%2,%3};"
        : "+f"(d[0]), "+f"(d[1]), "+f"(d[2]), "+f"(d[3])
        : "r"(a[0]), "r"(a[1]), "r"(a[2]), "r"(a[3]), "r"(b0), "r"(b1));
}

// gelu(v) = v * sigmoid(2z),  z = 0.79788456(v + 0.044715 v^3)
__device__ __forceinline__ float gelu_f(float v) {
    const float z2 = 1.5957691216057308f * (v + 0.044715f * v * v * v);
    return v / (1.f + __expf(-z2));
}

// ---------------- small kernels ----------------
__global__ void zero_cnt_kernel() { if (threadIdx.x < NE) g_cnt[threadIdx.x] = 0; }

__global__ void gate_kernel(const float* __restrict__ x,
                            const float* __restrict__ Wg,
                            const float* __restrict__ bg) {
    __shared__ float sWg[DM * NE];
    const int tid = threadIdx.x;
    for (int i = tid; i < DM * NE; i += 256) sWg[i] = Wg[i];
    __syncthreads();
    const int warp = tid >> 5, lane = tid & 31;
    const int t = blockIdx.x * 8 + warp;
    const float* xr = x + (size_t)t * DM;
    float acc[NE];
#pragma unroll
    for (int e = 0; e < NE; e++) acc[e] = 0.f;
    for (int i = 0; i < DM / 32; i++) {
        const int r = i * 32 + lane;
        const float xv = xr[r];
#pragma unroll
        for (int e = 0; e < NE; e++) acc[e] += xv * sWg[r * NE + e];
    }
#pragma unroll
    for (int e = 0; e < NE; e++)
#pragma unroll
        for (int off = 16; off > 0; off >>= 1)
            acc[e] += __shfl_xor_sync(0xFFFFFFFFu, acc[e], off);
    if (lane == 0) {
        float v[NE];
#pragma unroll
        for (int e = 0; e < NE; e++) v[e] = acc[e] + bg[e];
        int b0 = 0; float m0v = v[0];
#pragma unroll
        for (int e = 1; e < NE; e++) if (v[e] > m0v) { m0v = v[e]; b0 = e; }
        int b1i = (b0 == 0) ? 1 : 0; float m1v = v[(b0 == 0) ? 1 : 0];
#pragma unroll
        for (int e = 0; e < NE; e++)
            if (e != b0 && v[e] > m1v) { m1v = v[e]; b1i = e; }
        const float e1 = expf(m1v - m0v);
        const float s = 1.f + e1;
        int p = atomicAdd(&g_cnt[b0], 1);
        g_tok[b0 * TOKENS + p] = t; g_gate[b0 * TOKENS + p] = 1.f / s;
        p = atomicAdd(&g_cnt[b1i], 1);
        g_tok[b1i * TOKENS + p] = t; g_gate[b1i * TOKENS + p] = e1 / s;
    }
}

// converts x and W1 to fp16 (8 floats per thread) -- side stream, || gate
#define XBLK  ((TOKENS * DM / 8) / 256)                       // 2048
#define WBLK  ((int)((NE * (size_t)DM * DFF / 8) / 256))      // 16384
__global__ void convert_xw1_kernel(const float* __restrict__ x,
                                   const float* __restrict__ W1) {
    const int b = blockIdx.x;
    const float* src;
    __half* dst;
    size_t i;
    if (b < XBLK) {
        src = x;   dst = g_xh;  i = (size_t)b * 256 + threadIdx.x;
    } else {
        src = W1;  dst = g_w1h; i = (size_t)(b - XBLK) * 256 + threadIdx.x;
    }
    float4 a = ((const float4*)src)[2 * i];
    float4 c = ((const float4*)src)[2 * i + 1];
    __half h[8] = { __float2half_rn(a.x), __float2half_rn(a.y),
                    __float2half_rn(a.z), __float2half_rn(a.w),
                    __float2half_rn(c.x), __float2half_rn(c.y),
                    __float2half_rn(c.z), __float2half_rn(c.w) };
    ((uint4*)dst)[i] = *(uint4*)h;
}

// converts W2 to fp16 (side stream, overlaps gemm1's window)
__global__ void convert_w2_kernel(const float* __restrict__ W2) {
    const size_t i = (size_t)blockIdx.x * 256 + threadIdx.x;
    float4 a = ((const float4*)W2)[2 * i];
    float4 c = ((const float4*)W2)[2 * i + 1];
    __half h[8] = { __float2half_rn(a.x), __float2half_rn(a.y),
                    __float2half_rn(a.z), __float2half_rn(a.w),
                    __float2half_rn(c.x), __float2half_rn(c.y),
                    __float2half_rn(c.z), __float2half_rn(c.w) };
    ((uint4*)g_w2h)[i] = *(uint4*)h;
}

// ---------------- grouped GEMMs: exact R10 config (best measured) ----------------
// 128x128 tile, K-chunk 32, 8 warps 2x4 (warp tile 64x32), 4-stage cp.async,
// wait_group(2) + one __syncthreads per chunk. ~95% of mma.sync MAC roofline.
// PHASE 2 epilogue scatters gate*(v+bias) straight into out via atomicAdd
// (2 commutative addends per element -> deterministic; out pre-zeroed).
#define ASTRIDE 40
#define BSTRIDE 136
#define ASTAGE  (128 * ASTRIDE * 2)
#define BSTAGE  (32 * BSTRIDE * 2)
#define STAGES  4
#define SMEM_GEMM (STAGES * (ASTAGE + BSTAGE))

template<int PHASE>
__global__ void __launch_bounds__(256, 2)
moe_gemm_kernel(const float* __restrict__ bias_g, float* __restrict__ out) {
    constexpr int KDIM = (PHASE == 1) ? DM : DFF;
    constexpr int NDIM = (PHASE == 1) ? DFF : DM;
    constexpr int NK = KDIM / 32;

    const __half* __restrict__ Wh = (PHASE == 1) ? g_w1h : g_w2h;  // device-side resolve

    const int e  = blockIdx.y;
    const int c  = g_cnt[e];
    const int m0 = blockIdx.x * 128;          // m innermost
    if (m0 >= c) return;
    const int n0 = blockIdx.z * 128;          // n outermost

    extern __shared__ __align__(1024) char smem[];
    const uint32_t su = smem_to_u32(smem);
    const uint32_t sA = su, sB = su + STAGES * ASTAGE;

    const int tid = threadIdx.x;
    const int wid = tid >> 5, lane = tid & 31;
    const int warp_m = wid >> 2, warp_n = wid & 3;   // 2 x 4, warp tile 64x32

    // ---- A source (fp16): row = tid>>1, 2 x 16B per thread ----
    const int arow = tid >> 1, ac0 = (tid & 1) * 2;
    const int slotA = m0 + arow;
    const bool avalid = slotA < c;
    const __half* aptr;
    if (PHASE == 1) {
        const int tok = avalid ? g_tok[e * TOKENS + slotA] : 0;
        aptr = g_xh + (size_t)tok * DM;
    } else {
        aptr = g_h + ((size_t)e * TOKENS + (avalid ? slotA : 0)) * DFF;
    }
    const uint32_t abytes = (PHASE == 2 || avalid) ? 16u : 0u;

    // ---- B source (fp16): row = tid>>3 (32 rows), 16 halves per thread ----
    const int brow = tid >> 3, bcol = (tid & 7) * 16;
    const __half* bbase = Wh + (size_t)e * KDIM * NDIM + n0 + bcol;

    auto loadAB = [&](int kt, int s) {
        const uint32_t ad = sA + s * ASTAGE + (arow * ASTRIDE + ac0 * 8) * 2;
        const __half* as = aptr + kt * 32 + ac0 * 8;
        cp16(ad, as, abytes);
        cp16(ad + 16, as + 8, abytes);
        const uint32_t bd = sB + s * BSTAGE + (brow * BSTRIDE + bcol) * 2;
        const __half* bs = bbase + (size_t)(kt * 32 + brow) * NDIM;
        cp16(bd, bs, 16);
        cp16(bd + 16, bs + 8, 16);
    };

    float acc[4][4][4];
#pragma unroll
    for (int i = 0; i < 4; i++)
#pragma unroll
        for (int j = 0; j < 4; j++)
#pragma unroll
            for (int q = 0; q < 4; q++) acc[i][j][q] = 0.f;

    auto compute_stage = [&](int s) {
        const uint32_t ab = sA + s * ASTAGE;
        const uint32_t bb = sB + s * BSTAGE;
#pragma unroll
        for (int ks = 0; ks < 2; ks++) {
            uint32_t af[4][4];
#pragma unroll
            for (int mt = 0; mt < 4; mt++) {
                const uint32_t addr = ab +
                    ((warp_m * 64 + mt * 16 + (lane & 15)) * ASTRIDE +
                     ks * 16 + (lane >> 4) * 8) * 2;
                ldm_x4(af[mt], addr);
            }
            uint32_t bf[2][4];
#pragma unroll
            for (int np = 0; np < 2; np++) {
                const uint32_t k = ks * 16 + (lane & 7) + ((lane >> 3) & 1) * 8;
                const uint32_t col = warp_n * 32 + np * 16 + (lane >> 4) * 8;
                ldm_x4_t(bf[np], bb + (k * BSTRIDE + col) * 2);
            }
#pragma unroll
            for (int mt = 0; mt < 4; mt++)
#pragma unroll
                for (int nt = 0; nt < 4; nt++)
                    mma16816(acc[mt][nt], af[mt],
                             bf[nt >> 1][(nt & 1) * 2], bf[nt >> 1][(nt & 1) * 2 + 1]);
        }
    };

    // ---- prologue: fill stages 0..2 (3 commit groups) ----
#pragma unroll
    for (int p = 0; p < 3; p++) {
        if (p < NK) loadAB(p, p);
        CP_COMMIT();
    }

    // ---- mainloop: one sync per chunk; always commit so wait(2) <=> kt done ----
    for (int kt = 0; kt < NK; kt++) {
        asm volatile("cp.async.wait_group 2;" ::: "memory");
        __syncthreads();                    // stage kt readable; stage (kt+3)%4 free
        if (kt + 3 < NK) loadAB(kt + 3, (kt + 3) % STAGES);
        CP_COMMIT();
        compute_stage(kt % STAGES);
    }

    // ---- epilogue ----
    const float* bias = bias_g + (size_t)e * NDIM;
#pragma unroll
    for (int mt = 0; mt < 4; mt++) {
#pragma unroll
        for (int rh = 0; rh < 2; rh++) {
            const int r = warp_m * 64 + mt * 16 + (lane >> 2) + rh * 8;
            const int slot = m0 + r;
            if (slot < c) {
                int tok = 0; float gsc = 0.f;
                if (PHASE == 2) {
                    tok = g_tok[e * TOKENS + slot];
                    gsc = g_gate[e * TOKENS + slot];
                }
#pragma unroll
                for (int nt = 0; nt < 4; nt++) {
                    const int col = n0 + warp_n * 32 + nt * 8 + (lane & 3) * 2;
                    const float v0 = acc[mt][nt][rh * 2 + 0] + __ldg(&bias[col]);
                    const float v1 = acc[mt][nt][rh * 2 + 1] + __ldg(&bias[col + 1]);
                    if (PHASE == 1) {
                        __half2 hv = __floats2half2_rn(gelu_f(v0), gelu_f(v1));
                        *(__half2*)(g_h + ((size_t)e * TOKENS + slot) * DFF + col) = hv;
                    } else {
                        float* op = out + (size_t)tok * DM + col;
                        atomicAdd(op,     gsc * v0);
                        atomicAdd(op + 1, gsc * v1);
                    }
                }
            }
        }
    }
}

// ---------------- lazily-created side stream + events (host-side only; created
// on the uncaptured correctness call, so nothing is created during capture) ----
static cudaStream_t side_stream() {
    static cudaStream_t s = nullptr;
    if (!s) cudaStreamCreateWithFlags(&s, cudaStreamNonBlocking);
    return s;
}
static cudaEvent_t side_event(int i) {
    static cudaEvent_t e[3] = {nullptr, nullptr, nullptr};
    if (!e[i]) cudaEventCreateWithFlags(&e[i], cudaEventDisableTiming);
    return e[i];
}

// ---------------- launch ----------------
extern "C" void kernel_launch(void* const* d_in, const int* in_sizes, int n_in,
                              void* d_out, int out_size) {
    const float* x  = (const float*)d_in[0];
    const float* Wg = (const float*)d_in[1];
    const float* bg = (const float*)d_in[2];
    const float* W1 = (const float*)d_in[3];
    const float* b1 = (const float*)d_in[4];
    const float* W2 = (const float*)d_in[5];
    const float* b2 = (const float*)d_in[6];
    float* out = (float*)d_out;

    cudaFuncSetAttribute(moe_gemm_kernel<1>,
                         cudaFuncAttributeMaxDynamicSharedMemorySize, SMEM_GEMM);
    cudaFuncSetAttribute(moe_gemm_kernel<2>,
                         cudaFuncAttributeMaxDynamicSharedMemorySize, SMEM_GEMM);

    cudaStream_t s2 = side_stream();
    cudaEvent_t ev_fork = side_event(0), ev_xw1 = side_event(1), ev_s2 = side_event(2);

    // fork immediately: side stream does convert_xw1 (|| gate), then convert_w2
    // (|| gemm1), then zeroes out (|| gemm1).
    cudaEventRecord(ev_fork, 0);
    cudaStreamWaitEvent(s2, ev_fork, 0);
    convert_xw1_kernel<<<XBLK + WBLK, 256, 0, s2>>>(x, W1);
    cudaEventRecord(ev_xw1, s2);
    convert_w2_kernel<<<WBLK, 256, 0, s2>>>(W2);
    cudaMemsetAsync(out, 0, (size_t)TOKENS * DM * sizeof(float), s2);
    cudaEventRecord(ev_s2, s2);

    // main stream: gating runs concurrently with convert_xw1
    zero_cnt_kernel<<<1, 32>>>();
    gate_kernel<<<TOKENS / 8, 256>>>(x, Wg, bg);

    // gemm1 needs g_xh/g_w1h (ev_xw1) + gating (main-stream order)
    cudaStreamWaitEvent(0, ev_xw1, 0);
    dim3 g1(TOKENS / 128, NE, DFF / 128);   // m innermost, n outermost
    moe_gemm_kernel<1><<<g1, 256, SMEM_GEMM>>>(b1, nullptr);

    // gemm2 needs g_w2h + zeroed out (ev_s2); scatters directly into out
    cudaStreamWaitEvent(0, ev_s2, 0);
    dim3 g2(TOKENS / 128, NE, DM / 128);
    moe_gemm_kernel<2><<<g2, 256, SMEM_GEMM>>>(b2, out);
}